// round 14
// baseline (speedup 1.0000x reference)
#include <cuda_runtime.h>
#include <cuda_fp16.h>
#include <cstdint>

// ---------------------------------------------------------------------------
// PSAttention (B=32, CIN=2048, COUT=HW=1024), all-fp16 mma.sync (HMMA.16816).
//   Y1 = Wr @ X + br                  (B = X [c][n] natural, ldmatrix.trans)
//   [C;D] = [Wc;Wd] @ Y1 + [bc;bd]    (B = Y1 [c][n] natural, ldmatrix.trans)
//   C <- softmax_rows, D <- softmax_cols
//   out = Y1 + C @ D^T                (B = D [d][n'] K-major, normal path)
// R14: fragment double-buffering in the MMA loop; merged prep kernel.
// ---------------------------------------------------------------------------

#define NB 32
#define ELEMS (1024 * 1024)

__device__ __half  g_Xh  [NB * 2048 * 1024];   // X fp16, same layout as input
__device__ __half  g_Y1h [NB * ELEMS];         // Y1 fp16 [c][n]
__device__ __half  g_L   [NB * 2 * ELEMS];     // stacked logits [b][2048][1024]
__device__ __half  g_Ch  [NB * ELEMS];         // softmax C
__device__ __half  g_Dh  [NB * ELEMS];         // softmax D
__device__ __half  g_Wr  [1024 * 2048];
__device__ __half  g_Wcd [2 * ELEMS];          // [Wc; Wd]
__device__ float   g_Bcd [2048];               // [bc; bd]

// ---------------------------------------------------------------------------
// helpers
// ---------------------------------------------------------------------------
__device__ __forceinline__ uint32_t smem_u32(const void* p) {
    uint32_t a;
    asm("{ .reg .u64 t; cvta.to.shared.u64 t, %1; cvt.u32.u64 %0, t; }" : "=r"(a) : "l"(p));
    return a;
}
#define CP16(dst, src) \
    asm volatile("cp.async.cg.shared.global [%0], [%1], 16;" :: "r"(dst), "l"(src))

__device__ __forceinline__ uint32_t swz(uint32_t off) {       // SW128 (A / K-major B)
    return off ^ ((off >> 3) & 0x70);
}
__device__ __forceinline__ void ldsm4(uint32_t* r, uint32_t a) {
    asm volatile("ldmatrix.sync.aligned.m8n8.x4.shared.b16 {%0,%1,%2,%3}, [%4];"
        : "=r"(r[0]), "=r"(r[1]), "=r"(r[2]), "=r"(r[3]) : "r"(a));
}
__device__ __forceinline__ void ldsm4t(uint32_t* r, uint32_t a) {
    asm volatile("ldmatrix.sync.aligned.m8n8.x4.trans.shared.b16 {%0,%1,%2,%3}, [%4];"
        : "=r"(r[0]), "=r"(r[1]), "=r"(r[2]), "=r"(r[3]) : "r"(a));
}
__device__ __forceinline__ void mma16816(float* c, const uint32_t* a, const uint32_t* b) {
    asm volatile("mma.sync.aligned.m16n8k16.row.col.f32.f16.f16.f32 "
        "{%0,%1,%2,%3},{%4,%5,%6,%7},{%8,%9},{%0,%1,%2,%3};"
        : "+f"(c[0]), "+f"(c[1]), "+f"(c[2]), "+f"(c[3])
        : "r"(a[0]), "r"(a[1]), "r"(a[2]), "r"(a[3]), "r"(b[0]), "r"(b[1]));
}

// ---------------------------------------------------------------------------
// stage loaders. Stage = 48KB: A [128 rows x 128B, SW128] @ +0,
//   B @ +16384:
//     BTRANS=0: [256 n-rows x 128B K-major, SW128]
//     BTRANS=1: [64 k-rows x 512B n-contiguous, 16B-chunk XOR swizzle]
// ---------------------------------------------------------------------------
#define STAGE 49152u
template<int BTRANS>
__device__ __forceinline__ void load_stage(
    uint32_t sb, int s, int m0, int n0, int K, int ks0,
    const __half* A, const __half* B, int bStride, int tid)
{
    uint32_t buf = sb + (uint32_t)(s % 3) * STAGE;
#pragma unroll
    for (int i = 0; i < 4; i++) {          // A: 128 rows x 8 x 16B (K-major)
        int idx = tid + (i << 8);
        int r = idx >> 3, c = idx & 7;
        uint32_t sw = swz((uint32_t)(r * 128 + c * 16));
        CP16(buf + sw, A + (long)(m0 + r) * K + ks0 + (c << 3));
    }
    if (BTRANS) {
#pragma unroll
        for (int i = 0; i < 8; i++) {      // B: 64 k-rows x 32 x 16B chunks
            int idx = tid + (i << 8);
            int r = idx >> 5, c = idx & 31;
            uint32_t dst = buf + 16384u + (uint32_t)(r * 512 + ((c ^ (r & 7)) << 4));
            CP16(dst, B + (long)(ks0 + r) * bStride + n0 + (c << 3));
        }
    } else {
#pragma unroll
        for (int i = 0; i < 8; i++) {      // B: 256 n-rows x 8 x 16B (K-major)
            int idx = tid + (i << 8);
            int r = idx >> 3, c = idx & 7;
            uint32_t sw = swz((uint32_t)(r * 128 + c * 16));
            CP16(buf + 16384u + sw, B + (long)(n0 + r) * K + ks0 + (c << 3));
        }
    }
    asm volatile("cp.async.commit_group;" ::: "memory");
}

// ---------------------------------------------------------------------------
// GEMM: out[M,1024] per batch = A[M,K] @ B, fp16 operands, fp32 accum.
//   BTRANS=1: B given as [K][1024] natural (row stride bStride)
//   BTRANS=0: B given as [1024][K] K-major
// MODE 0: +bias[r], write fp16 outH (batch stride obatch)
// MODE 2: +fp16 addend, write fp32 outF
// CTA 128x256, 8 warps = 2(m) x 4(n), warp tile 64x64, 3-stage cp.async,
// double-buffered ldmatrix fragments (load ks+1 before MMAs of ks).
// ---------------------------------------------------------------------------
template<int BTRANS, int MODE>
__global__ __launch_bounds__(256, 1)
void gemm_mma(const __half* __restrict__ A_, long strideA,
              const __half* __restrict__ B_, long strideB, int bStride, int K,
              const float* __restrict__ bias,
              __half* __restrict__ outH, long obatch,
              const __half* __restrict__ addH,
              float* __restrict__ outF)
{
    extern __shared__ char smraw[];
    uint32_t sb = (smem_u32(smraw) + 1023u) & ~1023u;
    const int tid = threadIdx.x, lane = tid & 31, wid = tid >> 5;
    const int bz = blockIdx.z;
    const int m0 = blockIdx.y * 128, n0 = blockIdx.x * 256;

    const __half* A = A_ + (long)bz * strideA;
    const __half* B = B_ + (long)bz * strideB;

    const int wm0 = (wid & 1) * 64;
    const int wn0 = (wid >> 1) * 64;

    float acc[4][8][4];
#pragma unroll
    for (int a = 0; a < 4; a++)
#pragma unroll
        for (int b = 0; b < 8; b++)
#pragma unroll
            for (int c = 0; c < 4; c++) acc[a][b][c] = 0.0f;

    const int nC = K >> 6;
    load_stage<BTRANS>(sb, 0, m0, n0, K, 0,  A, B, bStride, tid);
    load_stage<BTRANS>(sb, 1, m0, n0, K, 64, A, B, bStride, tid);

    // A ldmatrix lane constants (K-major, SW128)
    const int      arow = wm0 + (lane & 15);
    const uint32_t akb0 = (uint32_t)((lane >> 4) * 16);
    // B K-major lane constants
    const int      brow = wn0 + (lane & 7) + ((lane >> 4) << 3);
    const uint32_t bkb0 = (uint32_t)(((lane >> 3) & 1) * 16);
    // B trans lane constants
    const int      tkr  = ((lane >> 3) & 1) * 8 + (lane & 7);  // k row within k16
    const int      tnc0 = (wn0 >> 3) + (lane >> 4);            // base n chunk

    uint32_t ahx[2][4][4], bbx[2][4][4];

    for (int s = 0; s < nC; s++) {
        if (s == nC - 1) asm volatile("cp.async.wait_group 0;" ::: "memory");
        else             asm volatile("cp.async.wait_group 1;" ::: "memory");
        __syncthreads();

        if (s + 2 < nC)
            load_stage<BTRANS>(sb, s + 2, m0, n0, K, (s + 2) << 6, A, B, bStride, tid);

        const uint32_t aB = sb + (uint32_t)(s % 3) * STAGE;
        const uint32_t bB = aB + 16384u;

        auto ldfrags = [&](int ks, uint32_t ah[4][4], uint32_t bb[4][4]) {
            const uint32_t akb = (uint32_t)(ks * 32) + akb0;
#pragma unroll
            for (int mt = 0; mt < 4; mt++)
                ldsm4(ah[mt], aB + swz((uint32_t)((arow + mt * 16) * 128) + akb));
            if (BTRANS) {
                const int kr = ks * 16 + tkr;
                const uint32_t rb = bB + (uint32_t)(kr * 512);
                const int sx = kr & 7;
#pragma unroll
                for (int q = 0; q < 4; q++)
                    ldsm4t(bb[q], rb + (uint32_t)(((tnc0 + 2 * q) ^ sx) << 4));
            } else {
                const uint32_t bkb = (uint32_t)(ks * 32) + bkb0;
#pragma unroll
                for (int q = 0; q < 4; q++)
                    ldsm4(bb[q], bB + swz((uint32_t)((brow + q * 16) * 128) + bkb));
            }
        };

        ldfrags(0, ahx[0], bbx[0]);
#pragma unroll
        for (int ks = 0; ks < 4; ks++) {
            if (ks < 3)
                ldfrags(ks + 1, ahx[(ks + 1) & 1], bbx[(ks + 1) & 1]);
            uint32_t (*ah)[4] = ahx[ks & 1];
            uint32_t (*bb)[4] = bbx[ks & 1];
#pragma unroll
            for (int mt = 0; mt < 4; mt++)
#pragma unroll
                for (int nb = 0; nb < 8; nb++)
                    mma16816(acc[mt][nb], ah[mt], &bb[nb >> 1][(nb & 1) * 2]);
        }
    }

    // ---- epilogue ----------------------------------------------------------
#pragma unroll
    for (int mt = 0; mt < 4; mt++) {
        const int r0 = m0 + wm0 + mt * 16 + (lane >> 2);
        float b0 = 0.0f, b1 = 0.0f;
        if (MODE == 0) { b0 = __ldg(&bias[r0]); b1 = __ldg(&bias[r0 + 8]); }
#pragma unroll
        for (int nb = 0; nb < 8; nb++) {
            const int col = n0 + wn0 + nb * 8 + (lane & 3) * 2;
            if (MODE == 0) {
                const long ob = (long)bz * obatch;
                float v0 = acc[mt][nb][0] + b0, v1 = acc[mt][nb][1] + b0;
                float v2 = acc[mt][nb][2] + b1, v3 = acc[mt][nb][3] + b1;
                *(__half2*)(outH + ob + (long)r0 * 1024 + col) = __floats2half2_rn(v0, v1);
                *(__half2*)(outH + ob + (long)(r0 + 8) * 1024 + col) = __floats2half2_rn(v2, v3);
            } else {
                const long ob = (long)bz << 20;
                const long i0 = ob + (long)r0 * 1024 + col;
                const long i1 = ob + (long)(r0 + 8) * 1024 + col;
                __half2 a0 = *(const __half2*)(addH + i0);
                __half2 a1 = *(const __half2*)(addH + i1);
                float v0 = acc[mt][nb][0] + __low2float(a0);
                float v1 = acc[mt][nb][1] + __high2float(a0);
                float v2 = acc[mt][nb][2] + __low2float(a1);
                float v3 = acc[mt][nb][3] + __high2float(a1);
                *(float2*)(outF + i0) = make_float2(v0, v1);
                *(float2*)(outF + i1) = make_float2(v2, v3);
            }
        }
    }
}

// ---------------------------------------------------------------------------
// conversions
// ---------------------------------------------------------------------------
// X fp32 -> fp16, same layout. 8 elements/thread.
__global__ void conv_x(const float4* __restrict__ X, uint4* __restrict__ o)
{
    long i = (long)blockIdx.x * 256 + threadIdx.x;
    float4 a = X[2 * i], b = X[2 * i + 1];
    __half2 h0 = __floats2half2_rn(a.x, a.y);
    __half2 h1 = __floats2half2_rn(a.z, a.w);
    __half2 h2 = __floats2half2_rn(b.x, b.y);
    __half2 h3 = __floats2half2_rn(b.z, b.w);
    uint4 v;
    v.x = *(uint32_t*)&h0; v.y = *(uint32_t*)&h1;
    v.z = *(uint32_t*)&h2; v.w = *(uint32_t*)&h3;
    o[i] = v;
}

// merged prep: Wr (2M) -> g_Wr, Wc (1M) -> g_Wcd[0:1M], Wd (1M) -> g_Wcd[1M:2M],
// bc/bd -> g_Bcd. One launch.
__global__ void prep_w(const float* __restrict__ wr, const float* __restrict__ wc,
                       const float* __restrict__ wd,
                       const float* __restrict__ bc, const float* __restrict__ bd,
                       __half* __restrict__ wrh, __half* __restrict__ wcd,
                       float* __restrict__ bcd)
{
    int i = blockIdx.x * 256 + threadIdx.x;          // grid covers 4M
    const int M2 = 2 * ELEMS, M3 = 3 * ELEMS;
    if (i < M2)      wrh[i] = __float2half(wr[i]);
    else if (i < M3) wcd[i - M2] = __float2half(wc[i - M2]);
    else             wcd[i - M2] = __float2half(wd[i - M3]);
    if (i < 1024)            bcd[i] = bc[i];
    else if (i < 2048)       bcd[i] = bd[i - 1024];
}

// ---------------------------------------------------------------------------
// softmaxes (fp16 logits in, fp16 out)
// ---------------------------------------------------------------------------
__global__ void row_softmax_h(const __half* __restrict__ L, __half* __restrict__ oh)
{
    const int b = blockIdx.x >> 10, c = blockIdx.x & 1023;
    const __half2* row = (const __half2*)(L + ((long)b * 2048 + c) * 1024);
    __half2* orow = (__half2*)(oh + ((long)b * 1024 + c) * 1024);
    const int t = threadIdx.x;            // 256 threads x 4 halves

    __half2 h0 = row[t * 2], h1 = row[t * 2 + 1];
    float v0 = __low2float(h0), v1 = __high2float(h0);
    float v2 = __low2float(h1), v3 = __high2float(h1);
    float m = fmaxf(fmaxf(v0, v1), fmaxf(v2, v3));

    __shared__ float red[256];
    red[t] = m; __syncthreads();
    for (int s = 128; s > 0; s >>= 1) { if (t < s) red[t] = fmaxf(red[t], red[t + s]); __syncthreads(); }
    m = red[0]; __syncthreads();

    float e0 = __expf(v0 - m), e1 = __expf(v1 - m);
    float e2 = __expf(v2 - m), e3 = __expf(v3 - m);
    red[t] = e0 + e1 + e2 + e3; __syncthreads();
    for (int s = 128; s > 0; s >>= 1) { if (t < s) red[t] += red[t + s]; __syncthreads(); }
    const float inv = 1.0f / red[0];

    orow[t * 2]     = __floats2half2_rn(e0 * inv, e1 * inv);
    orow[t * 2 + 1] = __floats2half2_rn(e2 * inv, e3 * inv);
}

__global__ void col_softmax_h(const __half* __restrict__ L, __half* __restrict__ oh)
{
    const int b = blockIdx.y;
    const int tx = threadIdx.x, ty = threadIdx.y;   // (32, 32)
    const int n = blockIdx.x * 32 + tx;
    const __half* basep = L + ((long)b * 2048 + 1024) * 1024 + n;
    __half* outp = oh + (long)b * ELEMS + n;

    __half vals[32];
#pragma unroll
    for (int i = 0; i < 32; i++)
        vals[i] = basep[(long)(ty + 32 * i) * 1024];

    float m = -1e30f;
#pragma unroll
    for (int i = 0; i < 32; i++) m = fmaxf(m, __half2float(vals[i]));

    __shared__ float red[32][33];
    red[ty][tx] = m; __syncthreads();
    m = -1e30f;
#pragma unroll
    for (int j = 0; j < 32; j++) m = fmaxf(m, red[j][tx]);
    __syncthreads();

    float e[32], s = 0.0f;
#pragma unroll
    for (int i = 0; i < 32; i++) { e[i] = __expf(__half2float(vals[i]) - m); s += e[i]; }
    red[ty][tx] = s; __syncthreads();
    s = 0.0f;
#pragma unroll
    for (int j = 0; j < 32; j++) s += red[j][tx];
    const float inv = 1.0f / s;

#pragma unroll
    for (int i = 0; i < 32; i++)
        outp[(long)(ty + 32 * i) * 1024] = __float2half(e[i] * inv);
}

// ---------------------------------------------------------------------------
// launch
// ---------------------------------------------------------------------------
#define SMEM_DYN (3 * 49152 + 1024)

extern "C" void kernel_launch(void* const* d_in, const int* in_sizes, int n_in,
                              void* d_out, int out_size)
{
    (void)in_sizes; (void)n_in; (void)out_size;

    const float* x  = (const float*)d_in[0];
    const float* wr = (const float*)d_in[1];
    const float* br = (const float*)d_in[2];
    const float* wc = (const float*)d_in[3];
    const float* bc = (const float*)d_in[4];
    const float* wd = (const float*)d_in[5];
    const float* bd = (const float*)d_in[6];
    float* out = (float*)d_out;

    __half *xh, *y1h, *lg, *ch, *dh, *wrh, *wcd;
    float* bcd;
    cudaGetSymbolAddress((void**)&xh,   g_Xh);
    cudaGetSymbolAddress((void**)&y1h,  g_Y1h);
    cudaGetSymbolAddress((void**)&lg,   g_L);
    cudaGetSymbolAddress((void**)&ch,   g_Ch);
    cudaGetSymbolAddress((void**)&dh,   g_Dh);
    cudaGetSymbolAddress((void**)&wrh,  g_Wr);
    cudaGetSymbolAddress((void**)&wcd,  g_Wcd);
    cudaGetSymbolAddress((void**)&bcd,  g_Bcd);

    cudaFuncSetAttribute((const void*)gemm_mma<1, 0>, cudaFuncAttributeMaxDynamicSharedMemorySize, SMEM_DYN);
    cudaFuncSetAttribute((const void*)gemm_mma<0, 2>, cudaFuncAttributeMaxDynamicSharedMemorySize, SMEM_DYN);

    // conversions
    prep_w<<<(4 * ELEMS) / 256, 256>>>(wr, wc, wd, bc, bd, wrh, wcd, bcd);
    conv_x<<<32768, 256>>>((const float4*)x, (uint4*)xh);   // 64M elems, 8/thread

    // GEMM1: Y1 = Wr @ X + br -> fp16 [c][n]  (B = Xh natural, trans path)
    gemm_mma<1, 0><<<dim3(4, 8, NB), 256, SMEM_DYN>>>(
        wrh, 0L, xh, (long)2048 * 1024, 1024, 2048, br, y1h, (long)ELEMS, nullptr, nullptr);

    // stacked GEMM2+3: [C;D] = [Wc;Wd] @ Y1 + [bc;bd]  (B = Y1h natural, trans path)
    gemm_mma<1, 0><<<dim3(4, 16, NB), 256, SMEM_DYN>>>(
        wcd, 0L, y1h, (long)ELEMS, 1024, 1024, bcd, lg, (long)2 * ELEMS, nullptr, nullptr);

    row_softmax_h<<<NB * 1024, 256>>>(lg, ch);
    col_softmax_h<<<dim3(32, NB), dim3(32, 32)>>>(lg, dh);

    // GEMM4: out = Y1 + C @ D^T  (B = Dh K-major, normal path)
    gemm_mma<0, 2><<<dim3(4, 8, NB), 256, SMEM_DYN>>>(
        ch, (long)ELEMS, dh, (long)ELEMS, 1024, 1024, nullptr, nullptr, 0L, y1h, out);
}

// round 15
// speedup vs baseline: 1.0150x; 1.0150x over previous
#include <cuda_runtime.h>
#include <cuda_fp16.h>
#include <cstdint>

// ---------------------------------------------------------------------------
// PSAttention (B=32, CIN=2048, COUT=HW=1024), all-fp16 mma.sync (HMMA.16816).
//   Y1 = Wr @ X + br                  (B = X [c][n] natural, ldmatrix.trans)
//   [C;D] = [Wc;Wd] @ Y1 + [bc;bd]    (B = Y1 [c][n] natural, ldmatrix.trans)
//   C <- softmax_rows, D <- softmax_cols
//   out = Y1 + C @ D^T                (B = D K-major, normal path)
// R15: 512-thread CTA, warp tile 64x32 -> ~115 regs/thread, 16 warps/SM.
// ---------------------------------------------------------------------------

#define NB 32
#define ELEMS (1024 * 1024)

__device__ __half  g_Xh  [NB * 2048 * 1024];   // X fp16, same layout as input
__device__ __half  g_Y1h [NB * ELEMS];         // Y1 fp16 [c][n]
__device__ __half  g_L   [NB * 2 * ELEMS];     // stacked logits [b][2048][1024]
__device__ __half  g_Ch  [NB * ELEMS];         // softmax C
__device__ __half  g_Dh  [NB * ELEMS];         // softmax D
__device__ __half  g_Wr  [1024 * 2048];
__device__ __half  g_Wcd [2 * ELEMS];          // [Wc; Wd]
__device__ float   g_Bcd [2048];               // [bc; bd]

// ---------------------------------------------------------------------------
// helpers
// ---------------------------------------------------------------------------
__device__ __forceinline__ uint32_t smem_u32(const void* p) {
    uint32_t a;
    asm("{ .reg .u64 t; cvta.to.shared.u64 t, %1; cvt.u32.u64 %0, t; }" : "=r"(a) : "l"(p));
    return a;
}
#define CP16(dst, src) \
    asm volatile("cp.async.cg.shared.global [%0], [%1], 16;" :: "r"(dst), "l"(src))

__device__ __forceinline__ uint32_t swz(uint32_t off) {       // SW128 (A / K-major B)
    return off ^ ((off >> 3) & 0x70);
}
__device__ __forceinline__ void ldsm4(uint32_t* r, uint32_t a) {
    asm volatile("ldmatrix.sync.aligned.m8n8.x4.shared.b16 {%0,%1,%2,%3}, [%4];"
        : "=r"(r[0]), "=r"(r[1]), "=r"(r[2]), "=r"(r[3]) : "r"(a));
}
__device__ __forceinline__ void ldsm4t(uint32_t* r, uint32_t a) {
    asm volatile("ldmatrix.sync.aligned.m8n8.x4.trans.shared.b16 {%0,%1,%2,%3}, [%4];"
        : "=r"(r[0]), "=r"(r[1]), "=r"(r[2]), "=r"(r[3]) : "r"(a));
}
__device__ __forceinline__ void mma16816(float* c, const uint32_t* a, const uint32_t* b) {
    asm volatile("mma.sync.aligned.m16n8k16.row.col.f32.f16.f16.f32 "
        "{%0,%1,%2,%3},{%4,%5,%6,%7},{%8,%9},{%0,%1,%2,%3};"
        : "+f"(c[0]), "+f"(c[1]), "+f"(c[2]), "+f"(c[3])
        : "r"(a[0]), "r"(a[1]), "r"(a[2]), "r"(a[3]), "r"(b[0]), "r"(b[1]));
}

// ---------------------------------------------------------------------------
// stage loaders (512 threads). Stage = 48KB: A [128 rows x 128B, SW128] @ +0,
//   B @ +16384:
//     BTRANS=0: [256 n-rows x 128B K-major, SW128]
//     BTRANS=1: [64 k-rows x 512B n-contiguous, 16B-chunk XOR swizzle]
// ---------------------------------------------------------------------------
#define STAGE 49152u
template<int BTRANS>
__device__ __forceinline__ void load_stage(
    uint32_t sb, int s, int m0, int n0, int K, int ks0,
    const __half* A, const __half* B, int bStride, int tid)
{
    uint32_t buf = sb + (uint32_t)(s % 3) * STAGE;
#pragma unroll
    for (int i = 0; i < 2; i++) {          // A: 128 rows x 8 x 16B (K-major)
        int idx = tid + (i << 9);
        int r = idx >> 3, c = idx & 7;
        uint32_t sw = swz((uint32_t)(r * 128 + c * 16));
        CP16(buf + sw, A + (long)(m0 + r) * K + ks0 + (c << 3));
    }
    if (BTRANS) {
#pragma unroll
        for (int i = 0; i < 4; i++) {      // B: 64 k-rows x 32 x 16B chunks
            int idx = tid + (i << 9);
            int r = idx >> 5, c = idx & 31;
            uint32_t dst = buf + 16384u + (uint32_t)(r * 512 + ((c ^ (r & 7)) << 4));
            CP16(dst, B + (long)(ks0 + r) * bStride + n0 + (c << 3));
        }
    } else {
#pragma unroll
        for (int i = 0; i < 4; i++) {      // B: 256 n-rows x 8 x 16B (K-major)
            int idx = tid + (i << 9);
            int r = idx >> 3, c = idx & 7;
            uint32_t sw = swz((uint32_t)(r * 128 + c * 16));
            CP16(buf + 16384u + sw, B + (long)(n0 + r) * K + ks0 + (c << 3));
        }
    }
    asm volatile("cp.async.commit_group;" ::: "memory");
}

// ---------------------------------------------------------------------------
// GEMM: out[M,1024] per batch = A[M,K] @ B, fp16 operands, fp32 accum.
//   BTRANS=1: B given as [K][1024] natural (row stride bStride)
//   BTRANS=0: B given as [1024][K] K-major
// MODE 0: +bias[r], write fp16 outH (batch stride obatch)
// MODE 2: +fp16 addend, write fp32 outF
// CTA 128x256, 16 warps = 2(m) x 8(n), warp tile 64x32, 3-stage cp.async.
// ---------------------------------------------------------------------------
template<int BTRANS, int MODE>
__global__ __launch_bounds__(512, 1)
void gemm_mma(const __half* __restrict__ A_, long strideA,
              const __half* __restrict__ B_, long strideB, int bStride, int K,
              const float* __restrict__ bias,
              __half* __restrict__ outH, long obatch,
              const __half* __restrict__ addH,
              float* __restrict__ outF)
{
    extern __shared__ char smraw[];
    uint32_t sb = (smem_u32(smraw) + 1023u) & ~1023u;
    const int tid = threadIdx.x, lane = tid & 31, wid = tid >> 5;
    const int bz = blockIdx.z;
    const int m0 = blockIdx.y * 128, n0 = blockIdx.x * 256;

    const __half* A = A_ + (long)bz * strideA;
    const __half* B = B_ + (long)bz * strideB;

    const int wm0 = (wid & 1) * 64;      // warp m offset
    const int wn0 = (wid >> 1) * 32;     // warp n offset (8 warps over 256)

    float acc[4][4][4];
#pragma unroll
    for (int a = 0; a < 4; a++)
#pragma unroll
        for (int b = 0; b < 4; b++)
#pragma unroll
            for (int c = 0; c < 4; c++) acc[a][b][c] = 0.0f;

    const int nC = K >> 6;
    load_stage<BTRANS>(sb, 0, m0, n0, K, 0,  A, B, bStride, tid);
    load_stage<BTRANS>(sb, 1, m0, n0, K, 64, A, B, bStride, tid);

    // A ldmatrix lane constants (K-major, SW128)
    const int      arow = wm0 + (lane & 15);
    const uint32_t akb0 = (uint32_t)((lane >> 4) * 16);
    // B K-major lane constants
    const int      brow = wn0 + (lane & 7) + ((lane >> 4) << 3);
    const uint32_t bkb0 = (uint32_t)(((lane >> 3) & 1) * 16);
    // B trans lane constants
    const int      tkr  = ((lane >> 3) & 1) * 8 + (lane & 7);  // k row within k16
    const int      tnc0 = (wn0 >> 3) + (lane >> 4);            // base n chunk

    for (int s = 0; s < nC; s++) {
        if (s == nC - 1) asm volatile("cp.async.wait_group 0;" ::: "memory");
        else             asm volatile("cp.async.wait_group 1;" ::: "memory");
        __syncthreads();

        if (s + 2 < nC)
            load_stage<BTRANS>(sb, s + 2, m0, n0, K, (s + 2) << 6, A, B, bStride, tid);

        const uint32_t aB = sb + (uint32_t)(s % 3) * STAGE;
        const uint32_t bB = aB + 16384u;

#pragma unroll
        for (int ks = 0; ks < 4; ks++) {
            uint32_t ah[4][4], bb[2][4];
            const uint32_t akb = (uint32_t)(ks * 32) + akb0;
#pragma unroll
            for (int mt = 0; mt < 4; mt++)
                ldsm4(ah[mt], aB + swz((uint32_t)((arow + mt * 16) * 128) + akb));
            if (BTRANS) {
                const int kr = ks * 16 + tkr;
                const uint32_t rb = bB + (uint32_t)(kr * 512);
                const int sx = kr & 7;
#pragma unroll
                for (int q = 0; q < 2; q++)
                    ldsm4t(bb[q], rb + (uint32_t)(((tnc0 + 2 * q) ^ sx) << 4));
            } else {
                const uint32_t bkb = (uint32_t)(ks * 32) + bkb0;
#pragma unroll
                for (int q = 0; q < 2; q++)
                    ldsm4(bb[q], bB + swz((uint32_t)((brow + q * 16) * 128) + bkb));
            }
#pragma unroll
            for (int mt = 0; mt < 4; mt++)
#pragma unroll
                for (int nb = 0; nb < 4; nb++)
                    mma16816(acc[mt][nb], ah[mt], &bb[nb >> 1][(nb & 1) * 2]);
        }
    }

    // ---- epilogue ----------------------------------------------------------
#pragma unroll
    for (int mt = 0; mt < 4; mt++) {
        const int r0 = m0 + wm0 + mt * 16 + (lane >> 2);
        float b0 = 0.0f, b1 = 0.0f;
        if (MODE == 0) { b0 = __ldg(&bias[r0]); b1 = __ldg(&bias[r0 + 8]); }
#pragma unroll
        for (int nb = 0; nb < 4; nb++) {
            const int col = n0 + wn0 + nb * 8 + (lane & 3) * 2;
            if (MODE == 0) {
                const long ob = (long)bz * obatch;
                float v0 = acc[mt][nb][0] + b0, v1 = acc[mt][nb][1] + b0;
                float v2 = acc[mt][nb][2] + b1, v3 = acc[mt][nb][3] + b1;
                *(__half2*)(outH + ob + (long)r0 * 1024 + col) = __floats2half2_rn(v0, v1);
                *(__half2*)(outH + ob + (long)(r0 + 8) * 1024 + col) = __floats2half2_rn(v2, v3);
            } else {
                const long ob = (long)bz << 20;
                const long i0 = ob + (long)r0 * 1024 + col;
                const long i1 = ob + (long)(r0 + 8) * 1024 + col;
                __half2 a0 = *(const __half2*)(addH + i0);
                __half2 a1 = *(const __half2*)(addH + i1);
                float v0 = acc[mt][nb][0] + __low2float(a0);
                float v1 = acc[mt][nb][1] + __high2float(a0);
                float v2 = acc[mt][nb][2] + __low2float(a1);
                float v3 = acc[mt][nb][3] + __high2float(a1);
                *(float2*)(outF + i0) = make_float2(v0, v1);
                *(float2*)(outF + i1) = make_float2(v2, v3);
            }
        }
    }
}

// ---------------------------------------------------------------------------
// conversions
// ---------------------------------------------------------------------------
// X fp32 -> fp16, same layout. 8 elements/thread.
__global__ void conv_x(const float4* __restrict__ X, uint4* __restrict__ o)
{
    long i = (long)blockIdx.x * 256 + threadIdx.x;
    float4 a = X[2 * i], b = X[2 * i + 1];
    __half2 h0 = __floats2half2_rn(a.x, a.y);
    __half2 h1 = __floats2half2_rn(a.z, a.w);
    __half2 h2 = __floats2half2_rn(b.x, b.y);
    __half2 h3 = __floats2half2_rn(b.z, b.w);
    uint4 v;
    v.x = *(uint32_t*)&h0; v.y = *(uint32_t*)&h1;
    v.z = *(uint32_t*)&h2; v.w = *(uint32_t*)&h3;
    o[i] = v;
}

// merged prep: Wr, Wc, Wd -> fp16; bc/bd -> bcd. One launch.
__global__ void prep_w(const float* __restrict__ wr, const float* __restrict__ wc,
                       const float* __restrict__ wd,
                       const float* __restrict__ bc, const float* __restrict__ bd,
                       __half* __restrict__ wrh, __half* __restrict__ wcd,
                       float* __restrict__ bcd)
{
    int i = blockIdx.x * 256 + threadIdx.x;          // grid covers 4M
    const int M2 = 2 * ELEMS, M3 = 3 * ELEMS;
    if (i < M2)      wrh[i] = __float2half(wr[i]);
    else if (i < M3) wcd[i - M2] = __float2half(wc[i - M2]);
    else             wcd[i - M2] = __float2half(wd[i - M3]);
    if (i < 1024)            bcd[i] = bc[i];
    else if (i < 2048)       bcd[i] = bd[i - 1024];
}

// ---------------------------------------------------------------------------
// softmaxes (fp16 logits in, fp16 out)
// ---------------------------------------------------------------------------
__global__ void row_softmax_h(const __half* __restrict__ L, __half* __restrict__ oh)
{
    const int b = blockIdx.x >> 10, c = blockIdx.x & 1023;
    const __half2* row = (const __half2*)(L + ((long)b * 2048 + c) * 1024);
    __half2* orow = (__half2*)(oh + ((long)b * 1024 + c) * 1024);
    const int t = threadIdx.x;            // 256 threads x 4 halves

    __half2 h0 = row[t * 2], h1 = row[t * 2 + 1];
    float v0 = __low2float(h0), v1 = __high2float(h0);
    float v2 = __low2float(h1), v3 = __high2float(h1);
    float m = fmaxf(fmaxf(v0, v1), fmaxf(v2, v3));

    __shared__ float red[256];
    red[t] = m; __syncthreads();
    for (int s = 128; s > 0; s >>= 1) { if (t < s) red[t] = fmaxf(red[t], red[t + s]); __syncthreads(); }
    m = red[0]; __syncthreads();

    float e0 = __expf(v0 - m), e1 = __expf(v1 - m);
    float e2 = __expf(v2 - m), e3 = __expf(v3 - m);
    red[t] = e0 + e1 + e2 + e3; __syncthreads();
    for (int s = 128; s > 0; s >>= 1) { if (t < s) red[t] += red[t + s]; __syncthreads(); }
    const float inv = 1.0f / red[0];

    orow[t * 2]     = __floats2half2_rn(e0 * inv, e1 * inv);
    orow[t * 2 + 1] = __floats2half2_rn(e2 * inv, e3 * inv);
}

__global__ void col_softmax_h(const __half* __restrict__ L, __half* __restrict__ oh)
{
    const int b = blockIdx.y;
    const int tx = threadIdx.x, ty = threadIdx.y;   // (32, 32)
    const int n = blockIdx.x * 32 + tx;
    const __half* basep = L + ((long)b * 2048 + 1024) * 1024 + n;
    __half* outp = oh + (long)b * ELEMS + n;

    __half vals[32];
#pragma unroll
    for (int i = 0; i < 32; i++)
        vals[i] = basep[(long)(ty + 32 * i) * 1024];

    float m = -1e30f;
#pragma unroll
    for (int i = 0; i < 32; i++) m = fmaxf(m, __half2float(vals[i]));

    __shared__ float red[32][33];
    red[ty][tx] = m; __syncthreads();
    m = -1e30f;
#pragma unroll
    for (int j = 0; j < 32; j++) m = fmaxf(m, red[j][tx]);
    __syncthreads();

    float e[32], s = 0.0f;
#pragma unroll
    for (int i = 0; i < 32; i++) { e[i] = __expf(__half2float(vals[i]) - m); s += e[i]; }
    red[ty][tx] = s; __syncthreads();
    s = 0.0f;
#pragma unroll
    for (int j = 0; j < 32; j++) s += red[j][tx];
    const float inv = 1.0f / s;

#pragma unroll
    for (int i = 0; i < 32; i++)
        outp[(long)(ty + 32 * i) * 1024] = __float2half(e[i] * inv);
}

// ---------------------------------------------------------------------------
// launch
// ---------------------------------------------------------------------------
#define SMEM_DYN (3 * 49152 + 1024)

extern "C" void kernel_launch(void* const* d_in, const int* in_sizes, int n_in,
                              void* d_out, int out_size)
{
    (void)in_sizes; (void)n_in; (void)out_size;

    const float* x  = (const float*)d_in[0];
    const float* wr = (const float*)d_in[1];
    const float* br = (const float*)d_in[2];
    const float* wc = (const float*)d_in[3];
    const float* bc = (const float*)d_in[4];
    const float* wd = (const float*)d_in[5];
    const float* bd = (const float*)d_in[6];
    float* out = (float*)d_out;

    __half *xh, *y1h, *lg, *ch, *dh, *wrh, *wcd;
    float* bcd;
    cudaGetSymbolAddress((void**)&xh,   g_Xh);
    cudaGetSymbolAddress((void**)&y1h,  g_Y1h);
    cudaGetSymbolAddress((void**)&lg,   g_L);
    cudaGetSymbolAddress((void**)&ch,   g_Ch);
    cudaGetSymbolAddress((void**)&dh,   g_Dh);
    cudaGetSymbolAddress((void**)&wrh,  g_Wr);
    cudaGetSymbolAddress((void**)&wcd,  g_Wcd);
    cudaGetSymbolAddress((void**)&bcd,  g_Bcd);

    cudaFuncSetAttribute((const void*)gemm_mma<1, 0>, cudaFuncAttributeMaxDynamicSharedMemorySize, SMEM_DYN);
    cudaFuncSetAttribute((const void*)gemm_mma<0, 2>, cudaFuncAttributeMaxDynamicSharedMemorySize, SMEM_DYN);

    // conversions
    prep_w<<<(4 * ELEMS) / 256, 256>>>(wr, wc, wd, bc, bd, wrh, wcd, bcd);
    conv_x<<<32768, 256>>>((const float4*)x, (uint4*)xh);   // 64M elems, 8/thread

    // GEMM1: Y1 = Wr @ X + br -> fp16 [c][n]  (B = Xh natural, trans path)
    gemm_mma<1, 0><<<dim3(4, 8, NB), 512, SMEM_DYN>>>(
        wrh, 0L, xh, (long)2048 * 1024, 1024, 2048, br, y1h, (long)ELEMS, nullptr, nullptr);

    // stacked GEMM2+3: [C;D] = [Wc;Wd] @ Y1 + [bc;bd]  (B = Y1h natural, trans path)
    gemm_mma<1, 0><<<dim3(4, 16, NB), 512, SMEM_DYN>>>(
        wcd, 0L, y1h, (long)ELEMS, 1024, 1024, bcd, lg, (long)2 * ELEMS, nullptr, nullptr);

    row_softmax_h<<<NB * 1024, 256>>>(lg, ch);
    col_softmax_h<<<dim3(32, NB), dim3(32, 32)>>>(lg, dh);

    // GEMM4: out = Y1 + C @ D^T  (B = Dh K-major, normal path)
    gemm_mma<0, 2><<<dim3(4, 8, NB), 512, SMEM_DYN>>>(
        ch, (long)ELEMS, dh, (long)ELEMS, 1024, 1024, nullptr, nullptr, 0L, y1h, out);
}

// round 16
// speedup vs baseline: 1.0770x; 1.0610x over previous
#include <cuda_runtime.h>
#include <cuda_fp16.h>
#include <cstdint>

// ---------------------------------------------------------------------------
// PSAttention (B=32, CIN=2048, COUT=HW=1024), all-fp16 mma.sync (HMMA.16816).
//   Y1 = Wr @ X + br                  (B = X [c][n] natural, ldmatrix.trans)
//   [C;D] = [Wc;Wd] @ Y1 + [bc;bd]    (B = Y1 [c][n] natural, ldmatrix.trans)
//   C <- softmax_rows, D <- softmax_cols
//   out = Y1 + C @ D^T                (B = D K-major, normal path)
// R16: CTA 128x128, 256 threads, 2 CTAs/SM (desynced barriers/epilogues).
// ---------------------------------------------------------------------------

#define NB 32
#define ELEMS (1024 * 1024)

__device__ __half  g_Xh  [NB * 2048 * 1024];   // X fp16, same layout as input
__device__ __half  g_Y1h [NB * ELEMS];         // Y1 fp16 [c][n]
__device__ __half  g_L   [NB * 2 * ELEMS];     // stacked logits [b][2048][1024]
__device__ __half  g_Ch  [NB * ELEMS];         // softmax C
__device__ __half  g_Dh  [NB * ELEMS];         // softmax D
__device__ __half  g_Wr  [1024 * 2048];
__device__ __half  g_Wcd [2 * ELEMS];          // [Wc; Wd]
__device__ float   g_Bcd [2048];               // [bc; bd]

// ---------------------------------------------------------------------------
// helpers
// ---------------------------------------------------------------------------
__device__ __forceinline__ uint32_t smem_u32(const void* p) {
    uint32_t a;
    asm("{ .reg .u64 t; cvta.to.shared.u64 t, %1; cvt.u32.u64 %0, t; }" : "=r"(a) : "l"(p));
    return a;
}
#define CP16(dst, src) \
    asm volatile("cp.async.cg.shared.global [%0], [%1], 16;" :: "r"(dst), "l"(src))

__device__ __forceinline__ uint32_t swz(uint32_t off) {       // SW128 (A / K-major B)
    return off ^ ((off >> 3) & 0x70);
}
__device__ __forceinline__ void ldsm4(uint32_t* r, uint32_t a) {
    asm volatile("ldmatrix.sync.aligned.m8n8.x4.shared.b16 {%0,%1,%2,%3}, [%4];"
        : "=r"(r[0]), "=r"(r[1]), "=r"(r[2]), "=r"(r[3]) : "r"(a));
}
__device__ __forceinline__ void ldsm4t(uint32_t* r, uint32_t a) {
    asm volatile("ldmatrix.sync.aligned.m8n8.x4.trans.shared.b16 {%0,%1,%2,%3}, [%4];"
        : "=r"(r[0]), "=r"(r[1]), "=r"(r[2]), "=r"(r[3]) : "r"(a));
}
__device__ __forceinline__ void mma16816(float* c, const uint32_t* a, const uint32_t* b) {
    asm volatile("mma.sync.aligned.m16n8k16.row.col.f32.f16.f16.f32 "
        "{%0,%1,%2,%3},{%4,%5,%6,%7},{%8,%9},{%0,%1,%2,%3};"
        : "+f"(c[0]), "+f"(c[1]), "+f"(c[2]), "+f"(c[3])
        : "r"(a[0]), "r"(a[1]), "r"(a[2]), "r"(a[3]), "r"(b[0]), "r"(b[1]));
}

// ---------------------------------------------------------------------------
// stage loaders (256 threads). Stage = 32KB: A [128 rows x 128B, SW128] @ +0,
//   B @ +16384 (16KB):
//     BTRANS=0: [128 n-rows x 128B K-major, SW128]
//     BTRANS=1: [64 k-rows x 256B n-contiguous, 8-row XOR chunk swizzle]
// ---------------------------------------------------------------------------
#define STAGE 32768u
template<int BTRANS>
__device__ __forceinline__ void load_stage(
    uint32_t sb, int s, int m0, int n0, int K, int ks0,
    const __half* A, const __half* B, int bStride, int tid)
{
    uint32_t buf = sb + (uint32_t)(s % 3) * STAGE;
#pragma unroll
    for (int i = 0; i < 4; i++) {          // A: 128 rows x 8 x 16B (K-major)
        int idx = tid + (i << 8);
        int r = idx >> 3, c = idx & 7;
        uint32_t sw = swz((uint32_t)(r * 128 + c * 16));
        CP16(buf + sw, A + (long)(m0 + r) * K + ks0 + (c << 3));
    }
    if (BTRANS) {
#pragma unroll
        for (int i = 0; i < 4; i++) {      // B: 64 k-rows x 16 x 16B chunks
            int idx = tid + (i << 8);
            int r = idx >> 4, c = idx & 15;
            uint32_t dst = buf + 16384u + (uint32_t)(r * 256 + ((c ^ (r & 7)) << 4));
            CP16(dst, B + (long)(ks0 + r) * bStride + n0 + (c << 3));
        }
    } else {
#pragma unroll
        for (int i = 0; i < 4; i++) {      // B: 128 n-rows x 8 x 16B (K-major)
            int idx = tid + (i << 8);
            int r = idx >> 3, c = idx & 7;
            uint32_t sw = swz((uint32_t)(r * 128 + c * 16));
            CP16(buf + 16384u + sw, B + (long)(n0 + r) * K + ks0 + (c << 3));
        }
    }
    asm volatile("cp.async.commit_group;" ::: "memory");
}

// ---------------------------------------------------------------------------
// GEMM: out[M,1024] per batch = A[M,K] @ B, fp16 operands, fp32 accum.
//   BTRANS=1: B given as [K][1024] natural (row stride bStride)
//   BTRANS=0: B given as [1024][K] K-major
// MODE 0: +bias[r], write fp16 outH (batch stride obatch)
// MODE 2: +fp16 addend, write fp32 outF
// CTA 128x128, 8 warps = 2(m) x 4(n), warp tile 64x32, 3-stage cp.async,
// 2 CTAs per SM.
// ---------------------------------------------------------------------------
template<int BTRANS, int MODE>
__global__ __launch_bounds__(256, 2)
void gemm_mma(const __half* __restrict__ A_, long strideA,
              const __half* __restrict__ B_, long strideB, int bStride, int K,
              const float* __restrict__ bias,
              __half* __restrict__ outH, long obatch,
              const __half* __restrict__ addH,
              float* __restrict__ outF)
{
    extern __shared__ char smraw[];
    uint32_t sb = (smem_u32(smraw) + 1023u) & ~1023u;
    const int tid = threadIdx.x, lane = tid & 31, wid = tid >> 5;
    const int bz = blockIdx.z;
    const int m0 = blockIdx.y * 128, n0 = blockIdx.x * 128;

    const __half* A = A_ + (long)bz * strideA;
    const __half* B = B_ + (long)bz * strideB;

    const int wm0 = (wid & 1) * 64;      // warp m offset
    const int wn0 = (wid >> 1) * 32;     // warp n offset (4 warps over 128)

    float acc[4][4][4];
#pragma unroll
    for (int a = 0; a < 4; a++)
#pragma unroll
        for (int b = 0; b < 4; b++)
#pragma unroll
            for (int c = 0; c < 4; c++) acc[a][b][c] = 0.0f;

    const int nC = K >> 6;
    load_stage<BTRANS>(sb, 0, m0, n0, K, 0,  A, B, bStride, tid);
    load_stage<BTRANS>(sb, 1, m0, n0, K, 64, A, B, bStride, tid);

    // A ldmatrix lane constants (K-major, SW128)
    const int      arow = wm0 + (lane & 15);
    const uint32_t akb0 = (uint32_t)((lane >> 4) * 16);
    // B K-major lane constants
    const int      brow = wn0 + (lane & 7) + ((lane >> 4) << 3);
    const uint32_t bkb0 = (uint32_t)(((lane >> 3) & 1) * 16);
    // B trans lane constants
    const int      tkr  = ((lane >> 3) & 1) * 8 + (lane & 7);  // k row within k16
    const int      tnc0 = (wn0 >> 3) + (lane >> 4);            // base n chunk

    for (int s = 0; s < nC; s++) {
        if (s == nC - 1) asm volatile("cp.async.wait_group 0;" ::: "memory");
        else             asm volatile("cp.async.wait_group 1;" ::: "memory");
        __syncthreads();

        if (s + 2 < nC)
            load_stage<BTRANS>(sb, s + 2, m0, n0, K, (s + 2) << 6, A, B, bStride, tid);

        const uint32_t aB = sb + (uint32_t)(s % 3) * STAGE;
        const uint32_t bB = aB + 16384u;

#pragma unroll
        for (int ks = 0; ks < 4; ks++) {
            uint32_t ah[4][4], bb[2][4];
            const uint32_t akb = (uint32_t)(ks * 32) + akb0;
#pragma unroll
            for (int mt = 0; mt < 4; mt++)
                ldsm4(ah[mt], aB + swz((uint32_t)((arow + mt * 16) * 128) + akb));
            if (BTRANS) {
                const int kr = ks * 16 + tkr;
                const uint32_t rb = bB + (uint32_t)(kr * 256);
                const int sx = kr & 7;
#pragma unroll
                for (int q = 0; q < 2; q++)
                    ldsm4t(bb[q], rb + (uint32_t)(((tnc0 + 2 * q) ^ sx) << 4));
            } else {
                const uint32_t bkb = (uint32_t)(ks * 32) + bkb0;
#pragma unroll
                for (int q = 0; q < 2; q++)
                    ldsm4(bb[q], bB + swz((uint32_t)((brow + q * 16) * 128) + bkb));
            }
#pragma unroll
            for (int mt = 0; mt < 4; mt++)
#pragma unroll
                for (int nb = 0; nb < 4; nb++)
                    mma16816(acc[mt][nb], ah[mt], &bb[nb >> 1][(nb & 1) * 2]);
        }
    }

    // ---- epilogue ----------------------------------------------------------
#pragma unroll
    for (int mt = 0; mt < 4; mt++) {
        const int r0 = m0 + wm0 + mt * 16 + (lane >> 2);
        float b0 = 0.0f, b1 = 0.0f;
        if (MODE == 0) { b0 = __ldg(&bias[r0]); b1 = __ldg(&bias[r0 + 8]); }
#pragma unroll
        for (int nb = 0; nb < 4; nb++) {
            const int col = n0 + wn0 + nb * 8 + (lane & 3) * 2;
            if (MODE == 0) {
                const long ob = (long)bz * obatch;
                float v0 = acc[mt][nb][0] + b0, v1 = acc[mt][nb][1] + b0;
                float v2 = acc[mt][nb][2] + b1, v3 = acc[mt][nb][3] + b1;
                *(__half2*)(outH + ob + (long)r0 * 1024 + col) = __floats2half2_rn(v0, v1);
                *(__half2*)(outH + ob + (long)(r0 + 8) * 1024 + col) = __floats2half2_rn(v2, v3);
            } else {
                const long ob = (long)bz << 20;
                const long i0 = ob + (long)r0 * 1024 + col;
                const long i1 = ob + (long)(r0 + 8) * 1024 + col;
                __half2 a0 = *(const __half2*)(addH + i0);
                __half2 a1 = *(const __half2*)(addH + i1);
                float v0 = acc[mt][nb][0] + __low2float(a0);
                float v1 = acc[mt][nb][1] + __high2float(a0);
                float v2 = acc[mt][nb][2] + __low2float(a1);
                float v3 = acc[mt][nb][3] + __high2float(a1);
                *(float2*)(outF + i0) = make_float2(v0, v1);
                *(float2*)(outF + i1) = make_float2(v2, v3);
            }
        }
    }
}

// ---------------------------------------------------------------------------
// conversions
// ---------------------------------------------------------------------------
// X fp32 -> fp16, same layout. 8 elements/thread.
__global__ void conv_x(const float4* __restrict__ X, uint4* __restrict__ o)
{
    long i = (long)blockIdx.x * 256 + threadIdx.x;
    float4 a = X[2 * i], b = X[2 * i + 1];
    __half2 h0 = __floats2half2_rn(a.x, a.y);
    __half2 h1 = __floats2half2_rn(a.z, a.w);
    __half2 h2 = __floats2half2_rn(b.x, b.y);
    __half2 h3 = __floats2half2_rn(b.z, b.w);
    uint4 v;
    v.x = *(uint32_t*)&h0; v.y = *(uint32_t*)&h1;
    v.z = *(uint32_t*)&h2; v.w = *(uint32_t*)&h3;
    o[i] = v;
}

// merged prep: Wr, Wc, Wd -> fp16; bc/bd -> bcd. One launch.
__global__ void prep_w(const float* __restrict__ wr, const float* __restrict__ wc,
                       const float* __restrict__ wd,
                       const float* __restrict__ bc, const float* __restrict__ bd,
                       __half* __restrict__ wrh, __half* __restrict__ wcd,
                       float* __restrict__ bcd)
{
    int i = blockIdx.x * 256 + threadIdx.x;          // grid covers 4M
    const int M2 = 2 * ELEMS, M3 = 3 * ELEMS;
    if (i < M2)      wrh[i] = __float2half(wr[i]);
    else if (i < M3) wcd[i - M2] = __float2half(wc[i - M2]);
    else             wcd[i - M2] = __float2half(wd[i - M3]);
    if (i < 1024)            bcd[i] = bc[i];
    else if (i < 2048)       bcd[i] = bd[i - 1024];
}

// ---------------------------------------------------------------------------
// softmaxes (fp16 logits in, fp16 out)
// ---------------------------------------------------------------------------
__global__ void row_softmax_h(const __half* __restrict__ L, __half* __restrict__ oh)
{
    const int b = blockIdx.x >> 10, c = blockIdx.x & 1023;
    const __half2* row = (const __half2*)(L + ((long)b * 2048 + c) * 1024);
    __half2* orow = (__half2*)(oh + ((long)b * 1024 + c) * 1024);
    const int t = threadIdx.x;            // 256 threads x 4 halves

    __half2 h0 = row[t * 2], h1 = row[t * 2 + 1];
    float v0 = __low2float(h0), v1 = __high2float(h0);
    float v2 = __low2float(h1), v3 = __high2float(h1);
    float m = fmaxf(fmaxf(v0, v1), fmaxf(v2, v3));

    __shared__ float red[256];
    red[t] = m; __syncthreads();
    for (int s = 128; s > 0; s >>= 1) { if (t < s) red[t] = fmaxf(red[t], red[t + s]); __syncthreads(); }
    m = red[0]; __syncthreads();

    float e0 = __expf(v0 - m), e1 = __expf(v1 - m);
    float e2 = __expf(v2 - m), e3 = __expf(v3 - m);
    red[t] = e0 + e1 + e2 + e3; __syncthreads();
    for (int s = 128; s > 0; s >>= 1) { if (t < s) red[t] += red[t + s]; __syncthreads(); }
    const float inv = 1.0f / red[0];

    orow[t * 2]     = __floats2half2_rn(e0 * inv, e1 * inv);
    orow[t * 2 + 1] = __floats2half2_rn(e2 * inv, e3 * inv);
}

__global__ void col_softmax_h(const __half* __restrict__ L, __half* __restrict__ oh)
{
    const int b = blockIdx.y;
    const int tx = threadIdx.x, ty = threadIdx.y;   // (32, 32)
    const int n = blockIdx.x * 32 + tx;
    const __half* basep = L + ((long)b * 2048 + 1024) * 1024 + n;
    __half* outp = oh + (long)b * ELEMS + n;

    __half vals[32];
#pragma unroll
    for (int i = 0; i < 32; i++)
        vals[i] = basep[(long)(ty + 32 * i) * 1024];

    float m = -1e30f;
#pragma unroll
    for (int i = 0; i < 32; i++) m = fmaxf(m, __half2float(vals[i]));

    __shared__ float red[32][33];
    red[ty][tx] = m; __syncthreads();
    m = -1e30f;
#pragma unroll
    for (int j = 0; j < 32; j++) m = fmaxf(m, red[j][tx]);
    __syncthreads();

    float e[32], s = 0.0f;
#pragma unroll
    for (int i = 0; i < 32; i++) { e[i] = __expf(__half2float(vals[i]) - m); s += e[i]; }
    red[ty][tx] = s; __syncthreads();
    s = 0.0f;
#pragma unroll
    for (int j = 0; j < 32; j++) s += red[j][tx];
    const float inv = 1.0f / s;

#pragma unroll
    for (int i = 0; i < 32; i++)
        outp[(long)(ty + 32 * i) * 1024] = __float2half(e[i] * inv);
}

// ---------------------------------------------------------------------------
// launch
// ---------------------------------------------------------------------------
#define SMEM_DYN (3 * 32768 + 1024)

extern "C" void kernel_launch(void* const* d_in, const int* in_sizes, int n_in,
                              void* d_out, int out_size)
{
    (void)in_sizes; (void)n_in; (void)out_size;

    const float* x  = (const float*)d_in[0];
    const float* wr = (const float*)d_in[1];
    const float* br = (const float*)d_in[2];
    const float* wc = (const float*)d_in[3];
    const float* bc = (const float*)d_in[4];
    const float* wd = (const float*)d_in[5];
    const float* bd = (const float*)d_in[6];
    float* out = (float*)d_out;

    __half *xh, *y1h, *lg, *ch, *dh, *wrh, *wcd;
    float* bcd;
    cudaGetSymbolAddress((void**)&xh,   g_Xh);
    cudaGetSymbolAddress((void**)&y1h,  g_Y1h);
    cudaGetSymbolAddress((void**)&lg,   g_L);
    cudaGetSymbolAddress((void**)&ch,   g_Ch);
    cudaGetSymbolAddress((void**)&dh,   g_Dh);
    cudaGetSymbolAddress((void**)&wrh,  g_Wr);
    cudaGetSymbolAddress((void**)&wcd,  g_Wcd);
    cudaGetSymbolAddress((void**)&bcd,  g_Bcd);

    cudaFuncSetAttribute((const void*)gemm_mma<1, 0>, cudaFuncAttributeMaxDynamicSharedMemorySize, SMEM_DYN);
    cudaFuncSetAttribute((const void*)gemm_mma<0, 2>, cudaFuncAttributeMaxDynamicSharedMemorySize, SMEM_DYN);

    // conversions
    prep_w<<<(4 * ELEMS) / 256, 256>>>(wr, wc, wd, bc, bd, wrh, wcd, bcd);
    conv_x<<<32768, 256>>>((const float4*)x, (uint4*)xh);   // 64M elems, 8/thread

    // GEMM1: Y1 = Wr @ X + br -> fp16 [c][n]  (B = Xh natural, trans path)
    gemm_mma<1, 0><<<dim3(8, 8, NB), 256, SMEM_DYN>>>(
        wrh, 0L, xh, (long)2048 * 1024, 1024, 2048, br, y1h, (long)ELEMS, nullptr, nullptr);

    // stacked GEMM2+3: [C;D] = [Wc;Wd] @ Y1 + [bc;bd]  (B = Y1h natural, trans path)
    gemm_mma<1, 0><<<dim3(8, 16, NB), 256, SMEM_DYN>>>(
        wcd, 0L, y1h, (long)ELEMS, 1024, 1024, bcd, lg, (long)2 * ELEMS, nullptr, nullptr);

    row_softmax_h<<<NB * 1024, 256>>>(lg, ch);
    col_softmax_h<<<dim3(32, NB), dim3(32, 32)>>>(lg, dh);

    // GEMM4: out = Y1 + C @ D^T  (B = Dh K-major, normal path)
    gemm_mma<0, 2><<<dim3(8, 8, NB), 256, SMEM_DYN>>>(
        ch, (long)ELEMS, dh, (long)ELEMS, 1024, 1024, nullptr, nullptr, 0L, y1h, out);
}

// round 17
// speedup vs baseline: 1.1223x; 1.0421x over previous
#include <cuda_runtime.h>
#include <cuda_fp16.h>
#include <cstdint>

// ---------------------------------------------------------------------------
// PSAttention (B=32, CIN=2048, COUT=HW=1024), all-fp16 mma.sync (HMMA.16816).
//   Y1 = Wr @ X + br                  (B = X [c][n] natural, ldmatrix.trans)
//   [C;D] = [Wc;Wd] @ Y1 + [bc;bd]    (B = Y1 [c][n] natural, ldmatrix.trans)
//   C <- softmax_rows, D <- softmax_cols
//   out = Y1 + C @ D^T                (B = D K-major, normal path)
// R17: warp-shuffle row softmax; merged prep+conv launch. GEMMs = R16.
// ---------------------------------------------------------------------------

#define NB 32
#define ELEMS (1024 * 1024)

__device__ __half  g_Xh  [NB * 2048 * 1024];   // X fp16, same layout as input
__device__ __half  g_Y1h [NB * ELEMS];         // Y1 fp16 [c][n]
__device__ __half  g_L   [NB * 2 * ELEMS];     // stacked logits [b][2048][1024]
__device__ __half  g_Ch  [NB * ELEMS];         // softmax C
__device__ __half  g_Dh  [NB * ELEMS];         // softmax D
__device__ __half  g_Wr  [1024 * 2048];
__device__ __half  g_Wcd [2 * ELEMS];          // [Wc; Wd]
__device__ float   g_Bcd [2048];               // [bc; bd]

// ---------------------------------------------------------------------------
// helpers
// ---------------------------------------------------------------------------
__device__ __forceinline__ uint32_t smem_u32(const void* p) {
    uint32_t a;
    asm("{ .reg .u64 t; cvta.to.shared.u64 t, %1; cvt.u32.u64 %0, t; }" : "=r"(a) : "l"(p));
    return a;
}
#define CP16(dst, src) \
    asm volatile("cp.async.cg.shared.global [%0], [%1], 16;" :: "r"(dst), "l"(src))

__device__ __forceinline__ uint32_t swz(uint32_t off) {       // SW128 (A / K-major B)
    return off ^ ((off >> 3) & 0x70);
}
__device__ __forceinline__ void ldsm4(uint32_t* r, uint32_t a) {
    asm volatile("ldmatrix.sync.aligned.m8n8.x4.shared.b16 {%0,%1,%2,%3}, [%4];"
        : "=r"(r[0]), "=r"(r[1]), "=r"(r[2]), "=r"(r[3]) : "r"(a));
}
__device__ __forceinline__ void ldsm4t(uint32_t* r, uint32_t a) {
    asm volatile("ldmatrix.sync.aligned.m8n8.x4.trans.shared.b16 {%0,%1,%2,%3}, [%4];"
        : "=r"(r[0]), "=r"(r[1]), "=r"(r[2]), "=r"(r[3]) : "r"(a));
}
__device__ __forceinline__ void mma16816(float* c, const uint32_t* a, const uint32_t* b) {
    asm volatile("mma.sync.aligned.m16n8k16.row.col.f32.f16.f16.f32 "
        "{%0,%1,%2,%3},{%4,%5,%6,%7},{%8,%9},{%0,%1,%2,%3};"
        : "+f"(c[0]), "+f"(c[1]), "+f"(c[2]), "+f"(c[3])
        : "r"(a[0]), "r"(a[1]), "r"(a[2]), "r"(a[3]), "r"(b[0]), "r"(b[1]));
}

// ---------------------------------------------------------------------------
// stage loaders (256 threads). Stage = 32KB: A [128 rows x 128B, SW128] @ +0,
//   B @ +16384 (16KB):
//     BTRANS=0: [128 n-rows x 128B K-major, SW128]
//     BTRANS=1: [64 k-rows x 256B n-contiguous, 8-row XOR chunk swizzle]
// ---------------------------------------------------------------------------
#define STAGE 32768u
template<int BTRANS>
__device__ __forceinline__ void load_stage(
    uint32_t sb, int s, int m0, int n0, int K, int ks0,
    const __half* A, const __half* B, int bStride, int tid)
{
    uint32_t buf = sb + (uint32_t)(s % 3) * STAGE;
#pragma unroll
    for (int i = 0; i < 4; i++) {          // A: 128 rows x 8 x 16B (K-major)
        int idx = tid + (i << 8);
        int r = idx >> 3, c = idx & 7;
        uint32_t sw = swz((uint32_t)(r * 128 + c * 16));
        CP16(buf + sw, A + (long)(m0 + r) * K + ks0 + (c << 3));
    }
    if (BTRANS) {
#pragma unroll
        for (int i = 0; i < 4; i++) {      // B: 64 k-rows x 16 x 16B chunks
            int idx = tid + (i << 8);
            int r = idx >> 4, c = idx & 15;
            uint32_t dst = buf + 16384u + (uint32_t)(r * 256 + ((c ^ (r & 7)) << 4));
            CP16(dst, B + (long)(ks0 + r) * bStride + n0 + (c << 3));
        }
    } else {
#pragma unroll
        for (int i = 0; i < 4; i++) {      // B: 128 n-rows x 8 x 16B (K-major)
            int idx = tid + (i << 8);
            int r = idx >> 3, c = idx & 7;
            uint32_t sw = swz((uint32_t)(r * 128 + c * 16));
            CP16(buf + 16384u + sw, B + (long)(n0 + r) * K + ks0 + (c << 3));
        }
    }
    asm volatile("cp.async.commit_group;" ::: "memory");
}

// ---------------------------------------------------------------------------
// GEMM: out[M,1024] per batch = A[M,K] @ B, fp16 operands, fp32 accum.
//   BTRANS=1: B given as [K][1024] natural (row stride bStride)
//   BTRANS=0: B given as [1024][K] K-major
// MODE 0: +bias[r], write fp16 outH (batch stride obatch)
// MODE 2: +fp16 addend, write fp32 outF
// CTA 128x128, 8 warps = 2(m) x 4(n), warp tile 64x32, 3-stage cp.async,
// 2 CTAs per SM.
// ---------------------------------------------------------------------------
template<int BTRANS, int MODE>
__global__ __launch_bounds__(256, 2)
void gemm_mma(const __half* __restrict__ A_, long strideA,
              const __half* __restrict__ B_, long strideB, int bStride, int K,
              const float* __restrict__ bias,
              __half* __restrict__ outH, long obatch,
              const __half* __restrict__ addH,
              float* __restrict__ outF)
{
    extern __shared__ char smraw[];
    uint32_t sb = (smem_u32(smraw) + 1023u) & ~1023u;
    const int tid = threadIdx.x, lane = tid & 31, wid = tid >> 5;
    const int bz = blockIdx.z;
    const int m0 = blockIdx.y * 128, n0 = blockIdx.x * 128;

    const __half* A = A_ + (long)bz * strideA;
    const __half* B = B_ + (long)bz * strideB;

    const int wm0 = (wid & 1) * 64;      // warp m offset
    const int wn0 = (wid >> 1) * 32;     // warp n offset (4 warps over 128)

    float acc[4][4][4];
#pragma unroll
    for (int a = 0; a < 4; a++)
#pragma unroll
        for (int b = 0; b < 4; b++)
#pragma unroll
            for (int c = 0; c < 4; c++) acc[a][b][c] = 0.0f;

    const int nC = K >> 6;
    load_stage<BTRANS>(sb, 0, m0, n0, K, 0,  A, B, bStride, tid);
    load_stage<BTRANS>(sb, 1, m0, n0, K, 64, A, B, bStride, tid);

    // A ldmatrix lane constants (K-major, SW128)
    const int      arow = wm0 + (lane & 15);
    const uint32_t akb0 = (uint32_t)((lane >> 4) * 16);
    // B K-major lane constants
    const int      brow = wn0 + (lane & 7) + ((lane >> 4) << 3);
    const uint32_t bkb0 = (uint32_t)(((lane >> 3) & 1) * 16);
    // B trans lane constants
    const int      tkr  = ((lane >> 3) & 1) * 8 + (lane & 7);  // k row within k16
    const int      tnc0 = (wn0 >> 3) + (lane >> 4);            // base n chunk

    for (int s = 0; s < nC; s++) {
        if (s == nC - 1) asm volatile("cp.async.wait_group 0;" ::: "memory");
        else             asm volatile("cp.async.wait_group 1;" ::: "memory");
        __syncthreads();

        if (s + 2 < nC)
            load_stage<BTRANS>(sb, s + 2, m0, n0, K, (s + 2) << 6, A, B, bStride, tid);

        const uint32_t aB = sb + (uint32_t)(s % 3) * STAGE;
        const uint32_t bB = aB + 16384u;

#pragma unroll
        for (int ks = 0; ks < 4; ks++) {
            uint32_t ah[4][4], bb[2][4];
            const uint32_t akb = (uint32_t)(ks * 32) + akb0;
#pragma unroll
            for (int mt = 0; mt < 4; mt++)
                ldsm4(ah[mt], aB + swz((uint32_t)((arow + mt * 16) * 128) + akb));
            if (BTRANS) {
                const int kr = ks * 16 + tkr;
                const uint32_t rb = bB + (uint32_t)(kr * 256);
                const int sx = kr & 7;
#pragma unroll
                for (int q = 0; q < 2; q++)
                    ldsm4t(bb[q], rb + (uint32_t)(((tnc0 + 2 * q) ^ sx) << 4));
            } else {
                const uint32_t bkb = (uint32_t)(ks * 32) + bkb0;
#pragma unroll
                for (int q = 0; q < 2; q++)
                    ldsm4(bb[q], bB + swz((uint32_t)((brow + q * 16) * 128) + bkb));
            }
#pragma unroll
            for (int mt = 0; mt < 4; mt++)
#pragma unroll
                for (int nb = 0; nb < 4; nb++)
                    mma16816(acc[mt][nb], ah[mt], &bb[nb >> 1][(nb & 1) * 2]);
        }
    }

    // ---- epilogue ----------------------------------------------------------
#pragma unroll
    for (int mt = 0; mt < 4; mt++) {
        const int r0 = m0 + wm0 + mt * 16 + (lane >> 2);
        float b0 = 0.0f, b1 = 0.0f;
        if (MODE == 0) { b0 = __ldg(&bias[r0]); b1 = __ldg(&bias[r0 + 8]); }
#pragma unroll
        for (int nb = 0; nb < 4; nb++) {
            const int col = n0 + wn0 + nb * 8 + (lane & 3) * 2;
            if (MODE == 0) {
                const long ob = (long)bz * obatch;
                float v0 = acc[mt][nb][0] + b0, v1 = acc[mt][nb][1] + b0;
                float v2 = acc[mt][nb][2] + b1, v3 = acc[mt][nb][3] + b1;
                *(__half2*)(outH + ob + (long)r0 * 1024 + col) = __floats2half2_rn(v0, v1);
                *(__half2*)(outH + ob + (long)(r0 + 8) * 1024 + col) = __floats2half2_rn(v2, v3);
            } else {
                const long ob = (long)bz << 20;
                const long i0 = ob + (long)r0 * 1024 + col;
                const long i1 = ob + (long)(r0 + 8) * 1024 + col;
                __half2 a0 = *(const __half2*)(addH + i0);
                __half2 a1 = *(const __half2*)(addH + i1);
                float v0 = acc[mt][nb][0] + __low2float(a0);
                float v1 = acc[mt][nb][1] + __high2float(a0);
                float v2 = acc[mt][nb][2] + __low2float(a1);
                float v3 = acc[mt][nb][3] + __high2float(a1);
                *(float2*)(outF + i0) = make_float2(v0, v1);
                *(float2*)(outF + i1) = make_float2(v2, v3);
            }
        }
    }
}

// ---------------------------------------------------------------------------
// merged prep: conv_x (64M elems fp32->fp16, 8/thread, blocks [0,32768)) +
// weight/bias conversion (4M elems, blocks [32768, 49152)). One launch.
// ---------------------------------------------------------------------------
__global__ void prep_all(const float4* __restrict__ X, uint4* __restrict__ xh,
                         const float* __restrict__ wr, const float* __restrict__ wc,
                         const float* __restrict__ wd,
                         const float* __restrict__ bc, const float* __restrict__ bd,
                         __half* __restrict__ wrh, __half* __restrict__ wcd,
                         float* __restrict__ bcd)
{
    if (blockIdx.x < 32768) {
        long i = (long)blockIdx.x * 256 + threadIdx.x;
        float4 a = X[2 * i], b = X[2 * i + 1];
        __half2 h0 = __floats2half2_rn(a.x, a.y);
        __half2 h1 = __floats2half2_rn(a.z, a.w);
        __half2 h2 = __floats2half2_rn(b.x, b.y);
        __half2 h3 = __floats2half2_rn(b.z, b.w);
        uint4 v;
        v.x = *(uint32_t*)&h0; v.y = *(uint32_t*)&h1;
        v.z = *(uint32_t*)&h2; v.w = *(uint32_t*)&h3;
        xh[i] = v;
    } else {
        int i = (blockIdx.x - 32768) * 256 + threadIdx.x;    // covers 4M
        const int M2 = 2 * ELEMS, M3 = 3 * ELEMS;
        if (i < M2)      wrh[i] = __float2half(wr[i]);
        else if (i < M3) wcd[i - M2] = __float2half(wc[i - M2]);
        else             wcd[i - M2] = __float2half(wd[i - M3]);
        if (i < 1024)            bcd[i] = bc[i];
        else if (i < 2048)       bcd[i] = bd[i - 1024];
    }
}

// ---------------------------------------------------------------------------
// softmaxes (fp16 logits in, fp16 out)
// ---------------------------------------------------------------------------
// rows: one warp per row, register-resident, shuffle reductions, no barriers.
// logits at [b*2048 + c][1024] -> Ch [b*1024 + c][1024]. 8 rows per block.
__global__ void row_softmax_h(const __half* __restrict__ L, __half* __restrict__ oh)
{
    const int w = threadIdx.x >> 5, lane = threadIdx.x & 31;
    const int row = blockIdx.x * 8 + w;
    const int b = row >> 10, c = row & 1023;
    const __half2* src = (const __half2*)(L + ((long)b * 2048 + c) * 1024);
    __half2* dst = (__half2*)(oh + ((long)b * 1024 + c) * 1024);

    float f[32];
    float m = -1e30f;
#pragma unroll
    for (int i = 0; i < 16; i++) {
        __half2 h = src[lane + 32 * i];
        f[2 * i]     = __low2float(h);
        f[2 * i + 1] = __high2float(h);
        m = fmaxf(m, fmaxf(f[2 * i], f[2 * i + 1]));
    }
#pragma unroll
    for (int o = 16; o > 0; o >>= 1)
        m = fmaxf(m, __shfl_xor_sync(0xFFFFFFFFu, m, o));

    float s = 0.0f;
#pragma unroll
    for (int i = 0; i < 32; i++) { f[i] = __expf(f[i] - m); s += f[i]; }
#pragma unroll
    for (int o = 16; o > 0; o >>= 1)
        s += __shfl_xor_sync(0xFFFFFFFFu, s, o);
    const float inv = 1.0f / s;

#pragma unroll
    for (int i = 0; i < 16; i++)
        dst[lane + 32 * i] = __floats2half2_rn(f[2 * i] * inv, f[2 * i + 1] * inv);
}

// cols: logits D at [b*2048 + 1024 + c][1024], softmax over c. Register-resident.
__global__ void col_softmax_h(const __half* __restrict__ L, __half* __restrict__ oh)
{
    const int b = blockIdx.y;
    const int tx = threadIdx.x, ty = threadIdx.y;   // (32, 32)
    const int n = blockIdx.x * 32 + tx;
    const __half* basep = L + ((long)b * 2048 + 1024) * 1024 + n;
    __half* outp = oh + (long)b * ELEMS + n;

    __half vals[32];
#pragma unroll
    for (int i = 0; i < 32; i++)
        vals[i] = basep[(long)(ty + 32 * i) * 1024];

    float m = -1e30f;
#pragma unroll
    for (int i = 0; i < 32; i++) m = fmaxf(m, __half2float(vals[i]));

    __shared__ float red[32][33];
    red[ty][tx] = m; __syncthreads();
    m = -1e30f;
#pragma unroll
    for (int j = 0; j < 32; j++) m = fmaxf(m, red[j][tx]);
    __syncthreads();

    float e[32], s = 0.0f;
#pragma unroll
    for (int i = 0; i < 32; i++) { e[i] = __expf(__half2float(vals[i]) - m); s += e[i]; }
    red[ty][tx] = s; __syncthreads();
    s = 0.0f;
#pragma unroll
    for (int j = 0; j < 32; j++) s += red[j][tx];
    const float inv = 1.0f / s;

#pragma unroll
    for (int i = 0; i < 32; i++)
        outp[(long)(ty + 32 * i) * 1024] = __float2half(e[i] * inv);
}

// ---------------------------------------------------------------------------
// launch
// ---------------------------------------------------------------------------
#define SMEM_DYN (3 * 32768 + 1024)

extern "C" void kernel_launch(void* const* d_in, const int* in_sizes, int n_in,
                              void* d_out, int out_size)
{
    (void)in_sizes; (void)n_in; (void)out_size;

    const float* x  = (const float*)d_in[0];
    const float* wr = (const float*)d_in[1];
    const float* br = (const float*)d_in[2];
    const float* wc = (const float*)d_in[3];
    const float* bc = (const float*)d_in[4];
    const float* wd = (const float*)d_in[5];
    const float* bd = (const float*)d_in[6];
    float* out = (float*)d_out;

    __half *xh, *y1h, *lg, *ch, *dh, *wrh, *wcd;
    float* bcd;
    cudaGetSymbolAddress((void**)&xh,   g_Xh);
    cudaGetSymbolAddress((void**)&y1h,  g_Y1h);
    cudaGetSymbolAddress((void**)&lg,   g_L);
    cudaGetSymbolAddress((void**)&ch,   g_Ch);
    cudaGetSymbolAddress((void**)&dh,   g_Dh);
    cudaGetSymbolAddress((void**)&wrh,  g_Wr);
    cudaGetSymbolAddress((void**)&wcd,  g_Wcd);
    cudaGetSymbolAddress((void**)&bcd,  g_Bcd);

    cudaFuncSetAttribute((const void*)gemm_mma<1, 0>, cudaFuncAttributeMaxDynamicSharedMemorySize, SMEM_DYN);
    cudaFuncSetAttribute((const void*)gemm_mma<0, 2>, cudaFuncAttributeMaxDynamicSharedMemorySize, SMEM_DYN);

    // conversions (single launch)
    prep_all<<<49152, 256>>>((const float4*)x, (uint4*)xh,
                             wr, wc, wd, bc, bd, wrh, wcd, bcd);

    // GEMM1: Y1 = Wr @ X + br -> fp16 [c][n]  (B = Xh natural, trans path)
    gemm_mma<1, 0><<<dim3(8, 8, NB), 256, SMEM_DYN>>>(
        wrh, 0L, xh, (long)2048 * 1024, 1024, 2048, br, y1h, (long)ELEMS, nullptr, nullptr);

    // stacked GEMM2+3: [C;D] = [Wc;Wd] @ Y1 + [bc;bd]  (B = Y1h natural, trans path)
    gemm_mma<1, 0><<<dim3(8, 16, NB), 256, SMEM_DYN>>>(
        wcd, 0L, y1h, (long)ELEMS, 1024, 1024, bcd, lg, (long)2 * ELEMS, nullptr, nullptr);

    row_softmax_h<<<NB * 128, 256>>>(lg, ch);
    col_softmax_h<<<dim3(32, NB), dim3(32, 32)>>>(lg, dh);

    // GEMM4: out = Y1 + C @ D^T  (B = Dh K-major, normal path)
    gemm_mma<0, 2><<<dim3(8, 8, NB), 256, SMEM_DYN>>>(
        ch, (long)ELEMS, dh, (long)ELEMS, 1024, 1024, nullptr, nullptr, 0L, y1h, out);
}